// round 9
// baseline (speedup 1.0000x reference)
#include <cuda_runtime.h>
#include <cuda_bf16.h>
#include <math.h>
#include <stdint.h>

// ---------------- problem constants ----------------
#define NLEV 3
#define MAXHW 65536
#define TOPK 1000
#define NTOT 3000              // 3 * TOPK
#define NW 47                  // ceil(3000/64)
#define NMS_TH 0.6f
#define CONF_TH 0.05f

// ---------------- device scratch (no allocations allowed) ----------------
__device__ unsigned            g_bits [NLEV][MAXHW];
__device__ int                 g_label[NLEV][MAXHW];
__device__ int                 g_cand [NLEV][MAXHW];
__device__ unsigned            t_bits [NTOT];
__device__ int                 t_label[NTOT];
__device__ float               t_box  [NTOT][4];
__device__ float               s_score[NTOT];
__device__ int                 s_label[NTOT];
__device__ float               s_box  [NTOT][4];
__device__ unsigned long long  g_mask [NTOT][NW];

__constant__ int   c_HW[3]   = {65536, 16384, 4096};
__constant__ int   c_W[3]    = {256, 128, 64};
__constant__ float c_strd[3] = {8.0f, 16.0f, 32.0f};

// ---------------- kernels ----------------

__device__ __forceinline__ float sigm(float x) { return 1.0f / (1.0f + expf(-x)); }

// warp-aggregated histogram add: lanes with equal key elect a leader which
// adds popc once. key==0xFFFFFFFF is a sentinel (no count). Convergent call.
__device__ __forceinline__ void hist_add(unsigned* hist, unsigned key, int lane) {
    unsigned m = __match_any_sync(0xFFFFFFFFu, key);
    if (key != 0xFFFFFFFFu && (__ffs(m) - 1) == lane)
        atomicAdd(&hist[key], (unsigned)__popc(m));
}

// fused decode, high-MLP: 1 thread/pixel, class loop in batches of 16
__global__ void __launch_bounds__(256) decode_all_kernel(
        const float* __restrict__ cls0,
        const float* __restrict__ cls1,
        const float* __restrict__ cls2,
        const float* __restrict__ ctn0,
        const float* __restrict__ ctn1,
        const float* __restrict__ ctn2) {
    int blk = blockIdx.x;
    int lv; const float* cls; const float* ctn; int HW;
    if (blk < 256)      { lv = 0; cls = cls0; ctn = ctn0; HW = 65536; }
    else if (blk < 320) { lv = 1; cls = cls1; ctn = ctn1; HW = 16384; blk -= 256; }
    else                { lv = 2; cls = cls2; ctn = ctn2; HW = 4096;  blk -= 320; }
    int i = blk * 256 + threadIdx.x;
    if (i >= HW) return;

    const float* p = cls + i;
    float m = -1e30f;
    int lab = 0;
    #pragma unroll
    for (int c0 = 0; c0 < 80; c0 += 16) {
        float v[16];
        #pragma unroll
        for (int k = 0; k < 16; k++) v[k] = p[(c0 + k) * HW];  // 16 independent loads
        #pragma unroll
        for (int k = 0; k < 16; k++)
            if (v[k] > m) { m = v[k]; lab = c0 + k; }          // in-order: first-max
    }

    float sc = sqrtf(sigm(m) * sigm(ctn[i]));
    g_bits[lv][i]  = __float_as_uint(sc);   // sc in (0,1): bits monotone in value
    g_label[lv][i] = lab;
}

// One block per level: two 256-bucket refinement passes (exact 16-bit bucket),
// compact, rank-count, emit topk. Histograms use warp-aggregated atomics.
__global__ void __launch_bounds__(1024) topk_level_kernel(
        const float* __restrict__ reg0,
        const float* __restrict__ reg1,
        const float* __restrict__ reg2,
        const float* __restrict__ scales) {
    int lv = blockIdx.x;
    const float* reg = (lv == 0) ? reg0 : (lv == 1) ? reg1 : reg2;
    int HW = c_HW[lv], W = c_W[lv];
    float stride = c_strd[lv];
    int tid = threadIdx.x;
    int lane = tid & 31;
    int n4 = HW >> 2;
    const uint4* b4 = (const uint4*)g_bits[lv];

    __shared__ unsigned hist[256];
    __shared__ unsigned suf[256];
    __shared__ int      sh_B;
    __shared__ unsigned sh_above;
    __shared__ int      sh_cnt;
    __shared__ unsigned long long skey[1024];

    // ---- pass 1: coarse hist over bits>>24 (warp-aggregated) ----
    if (tid < 256) hist[tid] = 0u;
    __syncthreads();
    for (int i = tid; i < n4; i += 1024) {
        uint4 v = b4[i];
        hist_add(hist, v.x >> 24, lane);
        hist_add(hist, v.y >> 24, lane);
        hist_add(hist, v.z >> 24, lane);
        hist_add(hist, v.w >> 24, lane);
    }
    __syncthreads();
    if (tid < 256) suf[tid] = hist[tid];
    __syncthreads();
    for (int off = 1; off < 256; off <<= 1) {
        unsigned add = (tid < 256 && tid + off < 256) ? suf[tid + off] : 0u;
        __syncthreads();
        if (tid < 256) suf[tid] += add;
        __syncthreads();
    }
    if (tid < 256) {
        bool ok  = suf[tid] >= (unsigned)TOPK;
        bool okn = (tid == 255) ? false : (suf[tid + 1] >= (unsigned)TOPK);
        if (ok && !okn) { sh_B = tid; sh_above = (tid == 255) ? 0u : suf[tid + 1]; }
    }
    __syncthreads();
    int B = sh_B;
    unsigned above = sh_above;

    // ---- pass 2: fine hist over (bits>>16)&0xFF within coarse bucket B ----
    if (tid < 256) hist[tid] = 0u;
    __syncthreads();
    for (int i = tid; i < n4; i += 1024) {
        uint4 v = b4[i];
        unsigned kx = ((int)(v.x >> 24) == B) ? ((v.x >> 16) & 0xFF) : 0xFFFFFFFFu;
        unsigned ky = ((int)(v.y >> 24) == B) ? ((v.y >> 16) & 0xFF) : 0xFFFFFFFFu;
        unsigned kz = ((int)(v.z >> 24) == B) ? ((v.z >> 16) & 0xFF) : 0xFFFFFFFFu;
        unsigned kw = ((int)(v.w >> 24) == B) ? ((v.w >> 16) & 0xFF) : 0xFFFFFFFFu;
        hist_add(hist, kx, lane);
        hist_add(hist, ky, lane);
        hist_add(hist, kz, lane);
        hist_add(hist, kw, lane);
    }
    __syncthreads();
    if (tid < 256) suf[tid] = hist[tid];
    __syncthreads();
    for (int off = 1; off < 256; off <<= 1) {
        unsigned add = (tid < 256 && tid + off < 256) ? suf[tid + off] : 0u;
        __syncthreads();
        if (tid < 256) suf[tid] += add;
        __syncthreads();
    }
    if (tid < 256) {
        bool ok  = above + suf[tid] >= (unsigned)TOPK;
        bool okn = (tid == 255) ? false : (above + suf[tid + 1] >= (unsigned)TOPK);
        if (ok && !okn) sh_B = ((B << 8) | tid);
    }
    __syncthreads();
    unsigned thresh = ((unsigned)sh_B) << 16;

    // ---- compact: indices with bits >= thresh (order irrelevant) ----
    if (tid == 0) sh_cnt = 0;
    __syncthreads();
    for (int i4 = tid; i4 < n4; i4 += 1024) {
        uint4 v = b4[i4];
        int i = i4 * 4;
        if (v.x >= thresh) g_cand[lv][atomicAdd(&sh_cnt, 1)] = i;
        if (v.y >= thresh) g_cand[lv][atomicAdd(&sh_cnt, 1)] = i + 1;
        if (v.z >= thresh) g_cand[lv][atomicAdd(&sh_cnt, 1)] = i + 2;
        if (v.w >= thresh) g_cand[lv][atomicAdd(&sh_cnt, 1)] = i + 3;
    }
    __syncthreads();
    int ncand = sh_cnt;

    // ---- rank candidates (value desc, index asc) and emit topk rows ----
    float scl = scales[lv];
    for (int cbase = 0; cbase < ncand; cbase += 1024) {
        int c = cbase + tid;
        bool active = (c < ncand);
        unsigned mybits = 0; int myidx = 0;
        unsigned long long mykey = 0;
        if (active) {
            myidx  = g_cand[lv][c];
            mybits = g_bits[lv][myidx];
            mykey  = ((unsigned long long)mybits << 32) | (unsigned)(~(unsigned)myidx);
        }
        int rank = 0;
        for (int base = 0; base < ncand; base += 1024) {
            int j = base + tid;
            unsigned long long k = 0;
            if (j < ncand) {
                int ji = g_cand[lv][j];
                k = ((unsigned long long)g_bits[lv][ji] << 32) | (unsigned)(~(unsigned)ji);
            }
            __syncthreads();
            skey[tid] = k;
            __syncthreads();
            int lim = min(1024, ncand - base);
            if (active)
                for (int t = 0; t < lim; t++) rank += (skey[t] > mykey) ? 1 : 0;
        }
        if (active && rank < TOPK) {
            int o = lv * TOPK + rank;
            t_bits[o]  = mybits;
            t_label[o] = g_label[lv][myidx];
            int x = myidx % W, y = myidx / W;
            float ax = ((float)x + 0.5f) * stride;
            float ay = ((float)y + 0.5f) * stride;
            float r0 = fmaxf(reg[0 * HW + myidx] * scl, 0.0f) * stride;
            float r1 = fmaxf(reg[1 * HW + myidx] * scl, 0.0f) * stride;
            float r2 = fmaxf(reg[2 * HW + myidx] * scl, 0.0f) * stride;
            float r3 = fmaxf(reg[3 * HW + myidx] * scl, 0.0f) * stride;
            t_box[o][0] = ax - r0; t_box[o][1] = ay - r1;
            t_box[o][2] = ax + r2; t_box[o][3] = ay + r3;
        }
        __syncthreads();
    }
}

// stable argsort(-scores) over the 3000 concatenated entries via rank counting
__global__ void rank_global_kernel() {
    int g = blockIdx.x * blockDim.x + threadIdx.x;
    __shared__ unsigned long long skey[256];
    bool active = (g < NTOT);
    unsigned long long mykey = 0;
    if (active) mykey = ((unsigned long long)t_bits[g] << 32) | (unsigned)(~(unsigned)g);
    int rank = 0;
    for (int base = 0; base < NTOT; base += 256) {
        int j = base + (int)threadIdx.x;
        unsigned long long k = 0;
        if (j < NTOT) k = ((unsigned long long)t_bits[j] << 32) | (unsigned)(~(unsigned)j);
        __syncthreads();
        skey[threadIdx.x] = k;
        __syncthreads();
        int lim = min(256, NTOT - base);
        if (active)
            for (int t = 0; t < lim; t++) rank += (skey[t] > mykey) ? 1 : 0;
    }
    if (active) {
        s_score[rank] = __uint_as_float(t_bits[g]);
        s_label[rank] = t_label[g];
        s_box[rank][0] = t_box[g][0];
        s_box[rank][1] = t_box[g][1];
        s_box[rank][2] = t_box[g][2];
        s_box[rank][3] = t_box[g][3];
    }
}

// suppression bitmask: bit j (j>i) set iff IoU(i,j) > 0.6
// triangle-pruned (skipped blocks are provably never read); exact IoU math
__global__ void mask_kernel() {
    int w  = blockIdx.x;                 // word 0..46  (j in [64w, 64w+64))
    int by = blockIdx.y;                 // i-block     (i in [256by, 256by+256))
    if (w < 4 * by) return;              // all j < all i in this block: never read
    __shared__ float jb[64][4];
    __shared__ float ja[64];
    int jlim = min(64, NTOT - w * 64);
    if ((int)threadIdx.x < jlim) {
        int j = w * 64 + threadIdx.x;
        float x1 = s_box[j][0], y1 = s_box[j][1], x2 = s_box[j][2], y2 = s_box[j][3];
        jb[threadIdx.x][0] = x1; jb[threadIdx.x][1] = y1;
        jb[threadIdx.x][2] = x2; jb[threadIdx.x][3] = y2;
        ja[threadIdx.x] = (x2 - x1) * (y2 - y1);
    }
    __syncthreads();
    int i = by * 256 + threadIdx.x;
    if (i >= NTOT) return;
    float ix1 = s_box[i][0], iy1 = s_box[i][1], ix2 = s_box[i][2], iy2 = s_box[i][3];
    float ia = (ix2 - ix1) * (iy2 - iy1);
    unsigned long long bits = 0;
    for (int b = 0; b < jlim; b++) {
        int j = w * 64 + b;
        if (j > i) {
            float xx1 = fmaxf(ix1, jb[b][0]);
            float yy1 = fmaxf(iy1, jb[b][1]);
            float xx2 = fminf(ix2, jb[b][2]);
            float yy2 = fminf(iy2, jb[b][3]);
            float ww = fmaxf(1e-10f, xx2 - xx1);
            float hh = fmaxf(1e-10f, yy2 - yy1);
            float inter = ww * hh;
            float iou = inter / (ia + ja[b] - inter + 1e-14f);
            if (iou > NMS_TH) bits |= (1ull << b);
        }
    }
    g_mask[i][w] = bits;
}

__device__ __forceinline__ unsigned long long warp_or64(unsigned long long v) {
    #pragma unroll
    for (int o = 16; o; o >>= 1) v |= __shfl_xor_sync(0xFFFFFFFFu, v, o);
    return v;
}

// Pipelined greedy NMS: 24 warps, warp k owns words {2k, 2k+1}.
__global__ void __launch_bounds__(768) nms_finalize_kernel(float* __restrict__ out) {
    __shared__ unsigned long long  sh_kept[NW];
    __shared__ unsigned long long  sh_remv[NW];
    __shared__ volatile int        sh_flag[NW];
    __shared__ unsigned long long  colbuf[24][64];
    int tid  = threadIdx.x;           // 768
    int warp = tid >> 5, lane = tid & 31;
    if (tid < NW) sh_flag[tid] = 0;
    __syncthreads();

    int w0 = warp * 2;
    int w1 = w0 + 1;                   // may be 47 (invalid for warp 23)
    bool has1 = (w1 < NW);
    int last = has1 ? w1 : w0;

    unsigned long long acc0 = 0ull, acc1 = 0ull;
    int rA = lane, rB = lane + 32;     // row offsets within a 64-block

    for (int c = 0; c <= last; c++) {
        int base = c * 64;
        unsigned long long m00 = (base + rA < NTOT) ? g_mask[base + rA][w0] : 0ull;
        unsigned long long m01 = (base + rB < NTOT) ? g_mask[base + rB][w0] : 0ull;
        unsigned long long m10 = 0ull, m11 = 0ull;
        if (has1) {
            m10 = (base + rA < NTOT) ? g_mask[base + rA][w1] : 0ull;
            m11 = (base + rB < NTOT) ? g_mask[base + rB][w1] : 0ull;
        }
        unsigned long long kept;
        if (c == w0 || c == w1) {
            unsigned long long mA = (c == w0) ? m00 : m10;
            unsigned long long mB = (c == w0) ? m01 : m11;
            colbuf[warp][lane]      = mA;
            colbuf[warp][lane + 32] = mB;
            __syncwarp();
            unsigned long long r = warp_or64((c == w0) ? acc0 : acc1);
            unsigned long long k0 = 0ull;
            if (lane == 0) {
                int lim = min(64, NTOT - base);
                #pragma unroll
                for (int b = 0; b < 64; b++) {
                    unsigned long long v = colbuf[warp][b];   // addr indep of r
                    if (!((r >> b) & 1ull)) { k0 |= (1ull << b); r |= v; }
                }
                if (lim < 64) k0 &= (1ull << lim) - 1ull;
                sh_remv[c] = r;
                sh_kept[c] = k0;
                __threadfence_block();
                sh_flag[c] = 1;
            }
            kept = __shfl_sync(0xFFFFFFFFu, k0, 0);
            __syncwarp();
        } else {
            while (sh_flag[c] == 0) {}
            __threadfence_block();
            kept = sh_kept[c];
        }
        if (c < w0) {
            acc0 |= (((kept >> rA) & 1ull) ? m00 : 0ull)
                  | (((kept >> rB) & 1ull) ? m01 : 0ull);
        }
        if (has1 && c < w1) {
            acc1 |= (((kept >> rA) & 1ull) ? m10 : 0ull)
                  | (((kept >> rB) & 1ull) ? m11 : 0ull);
        }
    }
    __syncthreads();

    // fused finalize: [boxes 12000][scores 3000][labels 3000][keep 3000] all f32
    for (int i = tid; i < NTOT; i += 768) {
        out[i * 4 + 0] = s_box[i][0];
        out[i * 4 + 1] = s_box[i][1];
        out[i * 4 + 2] = s_box[i][2];
        out[i * 4 + 3] = s_box[i][3];
        float sc = s_score[i];
        out[12000 + i] = sc;
        out[15000 + i] = (float)s_label[i];
        bool kp = !((sh_remv[i >> 6] >> (i & 63)) & 1ull) && (sc > CONF_TH);
        out[18000 + i] = kp ? 1.0f : 0.0f;
    }
}

// ---------------- launch ----------------
extern "C" void kernel_launch(void* const* d_in, const int* in_sizes, int n_in,
                              void* d_out, int out_size) {
    const float *cls[3], *reg[3], *ctn[3], *scales;
    if (in_sizes[1] == 262144) {
        cls[0] = (const float*)d_in[0]; reg[0] = (const float*)d_in[1]; ctn[0] = (const float*)d_in[2];
        cls[1] = (const float*)d_in[3]; reg[1] = (const float*)d_in[4]; ctn[1] = (const float*)d_in[5];
        cls[2] = (const float*)d_in[6]; reg[2] = (const float*)d_in[7]; ctn[2] = (const float*)d_in[8];
        scales = (const float*)d_in[9];
    } else if (in_sizes[3] == 262144) {
        cls[0] = (const float*)d_in[0]; cls[1] = (const float*)d_in[1]; cls[2] = (const float*)d_in[2];
        reg[0] = (const float*)d_in[3]; reg[1] = (const float*)d_in[4]; reg[2] = (const float*)d_in[5];
        ctn[0] = (const float*)d_in[6]; ctn[1] = (const float*)d_in[7]; ctn[2] = (const float*)d_in[8];
        scales = (const float*)d_in[9];
    } else {
        cls[0] = (const float*)d_in[0]; cls[1] = (const float*)d_in[1]; cls[2] = (const float*)d_in[2];
        ctn[0] = (const float*)d_in[3]; ctn[1] = (const float*)d_in[4]; ctn[2] = (const float*)d_in[5];
        reg[0] = (const float*)d_in[6]; reg[1] = (const float*)d_in[7]; reg[2] = (const float*)d_in[8];
        scales = (const float*)d_in[9];
    }

    decode_all_kernel<<<256 + 64 + 16, 256>>>(cls[0], cls[1], cls[2],
                                              ctn[0], ctn[1], ctn[2]);
    topk_level_kernel<<<3, 1024>>>(reg[0], reg[1], reg[2], scales);
    rank_global_kernel<<<(NTOT + 255) / 256, 256>>>();
    {
        dim3 grid(NW, (NTOT + 255) / 256);
        mask_kernel<<<grid, 256>>>();
    }
    nms_finalize_kernel<<<1, 768>>>((float*)d_out);
}

// round 10
// speedup vs baseline: 1.2361x; 1.2361x over previous
#include <cuda_runtime.h>
#include <cuda_bf16.h>
#include <math.h>
#include <stdint.h>

// ---------------- problem constants ----------------
#define NLEV 3
#define MAXHW 65536
#define TOPK 1000
#define NTOT 3000              // 3 * TOPK
#define NW 47                  // ceil(3000/64)
#define NMS_TH 0.6f
#define CONF_TH 0.05f

// ---------------- device scratch (no allocations allowed) ----------------
__device__ unsigned            g_bits [NLEV][MAXHW];
__device__ int                 g_label[NLEV][MAXHW];
__device__ int                 g_cand [NLEV][MAXHW];
__device__ unsigned            t_bits [NTOT];
__device__ int                 t_label[NTOT];
__device__ float               t_box  [NTOT][4];
__device__ float               s_score[NTOT];
__device__ int                 s_label[NTOT];
__device__ float               s_box  [NTOT][4];
__device__ unsigned long long  g_mask [NTOT][NW];
__device__ int                 g_dummy;

__constant__ int   c_HW[3]   = {65536, 16384, 4096};
__constant__ int   c_W[3]    = {256, 128, 64};
__constant__ float c_strd[3] = {8.0f, 16.0f, 32.0f};

// ---------------- kernels ----------------

__device__ __forceinline__ float sigm(float x) { return 1.0f / (1.0f + expf(-x)); }

// marker no-op (slot alignment so ncu's fixed capture slot lands on topk_level)
__global__ void marker_kernel(int v) { if (threadIdx.x == 1025) g_dummy = v; }

// fused decode, high-MLP: 1 thread/pixel, class loop in batches of 16
__global__ void __launch_bounds__(256) decode_all_kernel(
        const float* __restrict__ cls0,
        const float* __restrict__ cls1,
        const float* __restrict__ cls2,
        const float* __restrict__ ctn0,
        const float* __restrict__ ctn1,
        const float* __restrict__ ctn2) {
    int blk = blockIdx.x;
    int lv; const float* cls; const float* ctn; int HW;
    if (blk < 256)      { lv = 0; cls = cls0; ctn = ctn0; HW = 65536; }
    else if (blk < 320) { lv = 1; cls = cls1; ctn = ctn1; HW = 16384; blk -= 256; }
    else                { lv = 2; cls = cls2; ctn = ctn2; HW = 4096;  blk -= 320; }
    int i = blk * 256 + threadIdx.x;
    if (i >= HW) return;

    const float* p = cls + i;
    float m = -1e30f;
    int lab = 0;
    #pragma unroll
    for (int c0 = 0; c0 < 80; c0 += 16) {
        float v[16];
        #pragma unroll
        for (int k = 0; k < 16; k++) v[k] = p[(c0 + k) * HW];  // 16 independent loads
        #pragma unroll
        for (int k = 0; k < 16; k++)
            if (v[k] > m) { m = v[k]; lab = c0 + k; }          // in-order: first-max
    }

    float sc = sqrtf(sigm(m) * sigm(ctn[i]));
    g_bits[lv][i]  = __float_as_uint(sc);   // sc in (0,1): bits monotone in value
    g_label[lv][i] = lab;
}

// One block per level: two 256-bucket refinement passes (exact 16-bit bucket),
// compact, rank-count, emit topk. All sweeps uint4-vectorized (MLP 4).
__global__ void __launch_bounds__(1024) topk_level_kernel(
        const float* __restrict__ reg0,
        const float* __restrict__ reg1,
        const float* __restrict__ reg2,
        const float* __restrict__ scales) {
    int lv = blockIdx.x;
    const float* reg = (lv == 0) ? reg0 : (lv == 1) ? reg1 : reg2;
    int HW = c_HW[lv], W = c_W[lv];
    float stride = c_strd[lv];
    int tid = threadIdx.x;
    int n4 = HW >> 2;
    const uint4* b4 = (const uint4*)g_bits[lv];

    __shared__ unsigned hist[256];
    __shared__ unsigned suf[256];
    __shared__ int      sh_B;
    __shared__ unsigned sh_above;
    __shared__ int      sh_cnt;
    __shared__ unsigned long long skey[1024];

    // ---- pass 1: coarse hist over bits>>24 ----
    if (tid < 256) hist[tid] = 0u;
    __syncthreads();
    for (int i = tid; i < n4; i += 1024) {
        uint4 v = b4[i];
        atomicAdd(&hist[v.x >> 24], 1u);
        atomicAdd(&hist[v.y >> 24], 1u);
        atomicAdd(&hist[v.z >> 24], 1u);
        atomicAdd(&hist[v.w >> 24], 1u);
    }
    __syncthreads();
    if (tid < 256) suf[tid] = hist[tid];
    __syncthreads();
    for (int off = 1; off < 256; off <<= 1) {
        unsigned add = (tid < 256 && tid + off < 256) ? suf[tid + off] : 0u;
        __syncthreads();
        if (tid < 256) suf[tid] += add;
        __syncthreads();
    }
    if (tid < 256) {
        bool ok  = suf[tid] >= (unsigned)TOPK;
        bool okn = (tid == 255) ? false : (suf[tid + 1] >= (unsigned)TOPK);
        if (ok && !okn) { sh_B = tid; sh_above = (tid == 255) ? 0u : suf[tid + 1]; }
    }
    __syncthreads();
    int B = sh_B;
    unsigned above = sh_above;

    // ---- pass 2: fine hist over (bits>>16)&0xFF within coarse bucket B ----
    if (tid < 256) hist[tid] = 0u;
    __syncthreads();
    for (int i = tid; i < n4; i += 1024) {
        uint4 v = b4[i];
        if ((int)(v.x >> 24) == B) atomicAdd(&hist[(v.x >> 16) & 0xFF], 1u);
        if ((int)(v.y >> 24) == B) atomicAdd(&hist[(v.y >> 16) & 0xFF], 1u);
        if ((int)(v.z >> 24) == B) atomicAdd(&hist[(v.z >> 16) & 0xFF], 1u);
        if ((int)(v.w >> 24) == B) atomicAdd(&hist[(v.w >> 16) & 0xFF], 1u);
    }
    __syncthreads();
    if (tid < 256) suf[tid] = hist[tid];
    __syncthreads();
    for (int off = 1; off < 256; off <<= 1) {
        unsigned add = (tid < 256 && tid + off < 256) ? suf[tid + off] : 0u;
        __syncthreads();
        if (tid < 256) suf[tid] += add;
        __syncthreads();
    }
    if (tid < 256) {
        bool ok  = above + suf[tid] >= (unsigned)TOPK;
        bool okn = (tid == 255) ? false : (above + suf[tid + 1] >= (unsigned)TOPK);
        if (ok && !okn) sh_B = ((B << 8) | tid);
    }
    __syncthreads();
    unsigned thresh = ((unsigned)sh_B) << 16;

    // ---- compact: indices with bits >= thresh (order irrelevant) ----
    if (tid == 0) sh_cnt = 0;
    __syncthreads();
    for (int i4 = tid; i4 < n4; i4 += 1024) {
        uint4 v = b4[i4];
        int i = i4 * 4;
        if (v.x >= thresh) g_cand[lv][atomicAdd(&sh_cnt, 1)] = i;
        if (v.y >= thresh) g_cand[lv][atomicAdd(&sh_cnt, 1)] = i + 1;
        if (v.z >= thresh) g_cand[lv][atomicAdd(&sh_cnt, 1)] = i + 2;
        if (v.w >= thresh) g_cand[lv][atomicAdd(&sh_cnt, 1)] = i + 3;
    }
    __syncthreads();
    int ncand = sh_cnt;

    // ---- rank candidates (value desc, index asc) and emit topk rows ----
    float scl = scales[lv];
    for (int cbase = 0; cbase < ncand; cbase += 1024) {
        int c = cbase + tid;
        bool active = (c < ncand);
        unsigned mybits = 0; int myidx = 0;
        unsigned long long mykey = 0;
        if (active) {
            myidx  = g_cand[lv][c];
            mybits = g_bits[lv][myidx];
            mykey  = ((unsigned long long)mybits << 32) | (unsigned)(~(unsigned)myidx);
        }
        int rank = 0;
        for (int base = 0; base < ncand; base += 1024) {
            int j = base + tid;
            unsigned long long k = 0;
            if (j < ncand) {
                int ji = g_cand[lv][j];
                k = ((unsigned long long)g_bits[lv][ji] << 32) | (unsigned)(~(unsigned)ji);
            }
            __syncthreads();
            skey[tid] = k;
            __syncthreads();
            int lim = min(1024, ncand - base);
            if (active) {
                #pragma unroll 4
                for (int t = 0; t < lim; t++) rank += (skey[t] > mykey) ? 1 : 0;
            }
        }
        if (active && rank < TOPK) {
            int o = lv * TOPK + rank;
            t_bits[o]  = mybits;
            t_label[o] = g_label[lv][myidx];
            int x = myidx % W, y = myidx / W;
            float ax = ((float)x + 0.5f) * stride;
            float ay = ((float)y + 0.5f) * stride;
            float r0 = fmaxf(reg[0 * HW + myidx] * scl, 0.0f) * stride;
            float r1 = fmaxf(reg[1 * HW + myidx] * scl, 0.0f) * stride;
            float r2 = fmaxf(reg[2 * HW + myidx] * scl, 0.0f) * stride;
            float r3 = fmaxf(reg[3 * HW + myidx] * scl, 0.0f) * stride;
            t_box[o][0] = ax - r0; t_box[o][1] = ay - r1;
            t_box[o][2] = ax + r2; t_box[o][3] = ay + r3;
        }
        __syncthreads();
    }
}

// stable argsort(-scores) over the 3000 concatenated entries via rank counting
__global__ void rank_global_kernel() {
    int g = blockIdx.x * blockDim.x + threadIdx.x;
    __shared__ unsigned long long skey[256];
    bool active = (g < NTOT);
    unsigned long long mykey = 0;
    if (active) mykey = ((unsigned long long)t_bits[g] << 32) | (unsigned)(~(unsigned)g);
    int rank = 0;
    for (int base = 0; base < NTOT; base += 256) {
        int j = base + (int)threadIdx.x;
        unsigned long long k = 0;
        if (j < NTOT) k = ((unsigned long long)t_bits[j] << 32) | (unsigned)(~(unsigned)j);
        __syncthreads();
        skey[threadIdx.x] = k;
        __syncthreads();
        int lim = min(256, NTOT - base);
        if (active) {
            #pragma unroll 4
            for (int t = 0; t < lim; t++) rank += (skey[t] > mykey) ? 1 : 0;
        }
    }
    if (active) {
        s_score[rank] = __uint_as_float(t_bits[g]);
        s_label[rank] = t_label[g];
        s_box[rank][0] = t_box[g][0];
        s_box[rank][1] = t_box[g][1];
        s_box[rank][2] = t_box[g][2];
        s_box[rank][3] = t_box[g][3];
    }
}

// suppression bitmask: bit j (j>i) set iff IoU(i,j) > 0.6
// triangle-pruned (skipped blocks are provably never read); exact IoU math
__global__ void mask_kernel() {
    int w  = blockIdx.x;                 // word 0..46  (j in [64w, 64w+64))
    int by = blockIdx.y;                 // i-block     (i in [256by, 256by+256))
    if (w < 4 * by) return;              // all j < all i in this block: never read
    __shared__ float jb[64][4];
    __shared__ float ja[64];
    int jlim = min(64, NTOT - w * 64);
    if ((int)threadIdx.x < jlim) {
        int j = w * 64 + threadIdx.x;
        float x1 = s_box[j][0], y1 = s_box[j][1], x2 = s_box[j][2], y2 = s_box[j][3];
        jb[threadIdx.x][0] = x1; jb[threadIdx.x][1] = y1;
        jb[threadIdx.x][2] = x2; jb[threadIdx.x][3] = y2;
        ja[threadIdx.x] = (x2 - x1) * (y2 - y1);
    }
    __syncthreads();
    int i = by * 256 + threadIdx.x;
    if (i >= NTOT) return;
    float ix1 = s_box[i][0], iy1 = s_box[i][1], ix2 = s_box[i][2], iy2 = s_box[i][3];
    float ia = (ix2 - ix1) * (iy2 - iy1);
    unsigned long long bits = 0;
    for (int b = 0; b < jlim; b++) {
        int j = w * 64 + b;
        if (j > i) {
            float xx1 = fmaxf(ix1, jb[b][0]);
            float yy1 = fmaxf(iy1, jb[b][1]);
            float xx2 = fminf(ix2, jb[b][2]);
            float yy2 = fminf(iy2, jb[b][3]);
            float ww = fmaxf(1e-10f, xx2 - xx1);
            float hh = fmaxf(1e-10f, yy2 - yy1);
            float inter = ww * hh;
            float iou = inter / (ia + ja[b] - inter + 1e-14f);
            if (iou > NMS_TH) bits |= (1ull << b);
        }
    }
    g_mask[i][w] = bits;
}

__device__ __forceinline__ unsigned long long warp_or64(unsigned long long v) {
    #pragma unroll
    for (int o = 16; o; o >>= 1) v |= __shfl_xor_sync(0xFFFFFFFFu, v, o);
    return v;
}

// Pipelined greedy NMS: 24 warps, warp k owns words {2k, 2k+1}.
__global__ void __launch_bounds__(768) nms_finalize_kernel(float* __restrict__ out) {
    __shared__ unsigned long long  sh_kept[NW];
    __shared__ unsigned long long  sh_remv[NW];
    __shared__ volatile int        sh_flag[NW];
    __shared__ unsigned long long  colbuf[24][64];
    int tid  = threadIdx.x;           // 768
    int warp = tid >> 5, lane = tid & 31;
    if (tid < NW) sh_flag[tid] = 0;
    __syncthreads();

    int w0 = warp * 2;
    int w1 = w0 + 1;                   // may be 47 (invalid for warp 23)
    bool has1 = (w1 < NW);
    int last = has1 ? w1 : w0;

    unsigned long long acc0 = 0ull, acc1 = 0ull;
    int rA = lane, rB = lane + 32;     // row offsets within a 64-block

    for (int c = 0; c <= last; c++) {
        int base = c * 64;
        unsigned long long m00 = (base + rA < NTOT) ? g_mask[base + rA][w0] : 0ull;
        unsigned long long m01 = (base + rB < NTOT) ? g_mask[base + rB][w0] : 0ull;
        unsigned long long m10 = 0ull, m11 = 0ull;
        if (has1) {
            m10 = (base + rA < NTOT) ? g_mask[base + rA][w1] : 0ull;
            m11 = (base + rB < NTOT) ? g_mask[base + rB][w1] : 0ull;
        }
        unsigned long long kept;
        if (c == w0 || c == w1) {
            unsigned long long mA = (c == w0) ? m00 : m10;
            unsigned long long mB = (c == w0) ? m01 : m11;
            colbuf[warp][lane]      = mA;
            colbuf[warp][lane + 32] = mB;
            __syncwarp();
            unsigned long long r = warp_or64((c == w0) ? acc0 : acc1);
            unsigned long long k0 = 0ull;
            if (lane == 0) {
                int lim = min(64, NTOT - base);
                #pragma unroll
                for (int b = 0; b < 64; b++) {
                    unsigned long long v = colbuf[warp][b];   // addr indep of r
                    if (!((r >> b) & 1ull)) { k0 |= (1ull << b); r |= v; }
                }
                if (lim < 64) k0 &= (1ull << lim) - 1ull;
                sh_remv[c] = r;
                sh_kept[c] = k0;
                __threadfence_block();
                sh_flag[c] = 1;
            }
            kept = __shfl_sync(0xFFFFFFFFu, k0, 0);
            __syncwarp();
        } else {
            while (sh_flag[c] == 0) {}
            __threadfence_block();
            kept = sh_kept[c];
        }
        if (c < w0) {
            acc0 |= (((kept >> rA) & 1ull) ? m00 : 0ull)
                  | (((kept >> rB) & 1ull) ? m01 : 0ull);
        }
        if (has1 && c < w1) {
            acc1 |= (((kept >> rA) & 1ull) ? m10 : 0ull)
                  | (((kept >> rB) & 1ull) ? m11 : 0ull);
        }
    }
    __syncthreads();

    // fused finalize: [boxes 12000][scores 3000][labels 3000][keep 3000] all f32
    for (int i = tid; i < NTOT; i += 768) {
        out[i * 4 + 0] = s_box[i][0];
        out[i * 4 + 1] = s_box[i][1];
        out[i * 4 + 2] = s_box[i][2];
        out[i * 4 + 3] = s_box[i][3];
        float sc = s_score[i];
        out[12000 + i] = sc;
        out[15000 + i] = (float)s_label[i];
        bool kp = !((sh_remv[i >> 6] >> (i & 63)) & 1ull) && (sc > CONF_TH);
        out[18000 + i] = kp ? 1.0f : 0.0f;
    }
}

// ---------------- launch ----------------
extern "C" void kernel_launch(void* const* d_in, const int* in_sizes, int n_in,
                              void* d_out, int out_size) {
    const float *cls[3], *reg[3], *ctn[3], *scales;
    if (in_sizes[1] == 262144) {
        cls[0] = (const float*)d_in[0]; reg[0] = (const float*)d_in[1]; ctn[0] = (const float*)d_in[2];
        cls[1] = (const float*)d_in[3]; reg[1] = (const float*)d_in[4]; ctn[1] = (const float*)d_in[5];
        cls[2] = (const float*)d_in[6]; reg[2] = (const float*)d_in[7]; ctn[2] = (const float*)d_in[8];
        scales = (const float*)d_in[9];
    } else if (in_sizes[3] == 262144) {
        cls[0] = (const float*)d_in[0]; cls[1] = (const float*)d_in[1]; cls[2] = (const float*)d_in[2];
        reg[0] = (const float*)d_in[3]; reg[1] = (const float*)d_in[4]; reg[2] = (const float*)d_in[5];
        ctn[0] = (const float*)d_in[6]; ctn[1] = (const float*)d_in[7]; ctn[2] = (const float*)d_in[8];
        scales = (const float*)d_in[9];
    } else {
        cls[0] = (const float*)d_in[0]; cls[1] = (const float*)d_in[1]; cls[2] = (const float*)d_in[2];
        ctn[0] = (const float*)d_in[3]; ctn[1] = (const float*)d_in[4]; ctn[2] = (const float*)d_in[5];
        reg[0] = (const float*)d_in[6]; reg[1] = (const float*)d_in[7]; reg[2] = (const float*)d_in[8];
        scales = (const float*)d_in[9];
    }

    // markers shift ncu's fixed capture slot (#4) onto topk_level_kernel
    marker_kernel<<<1, 32>>>(1);
    marker_kernel<<<1, 32>>>(2);
    decode_all_kernel<<<256 + 64 + 16, 256>>>(cls[0], cls[1], cls[2],
                                              ctn[0], ctn[1], ctn[2]);
    topk_level_kernel<<<3, 1024>>>(reg[0], reg[1], reg[2], scales);
    rank_global_kernel<<<(NTOT + 255) / 256, 256>>>();
    {
        dim3 grid(NW, (NTOT + 255) / 256);
        mask_kernel<<<grid, 256>>>();
    }
    nms_finalize_kernel<<<1, 768>>>((float*)d_out);
}

// round 11
// speedup vs baseline: 1.3902x; 1.1246x over previous
#include <cuda_runtime.h>
#include <cuda_bf16.h>
#include <math.h>
#include <stdint.h>

// ---------------- problem constants ----------------
#define NLEV 3
#define MAXHW 65536
#define TOPK 1000
#define NTOT 3000              // 3 * TOPK
#define NW 47                  // ceil(3000/64)
#define NMS_TH 0.6f
#define CONF_TH 0.05f

// ---------------- device scratch (no allocations allowed) ----------------
__device__ unsigned            g_bits [NLEV][MAXHW];
__device__ int                 g_label[NLEV][MAXHW];
__device__ int                 g_cand [NLEV][MAXHW];
__device__ unsigned            t_bits [NTOT];
__device__ int                 t_label[NTOT];
__device__ float               t_box  [NTOT][4];
__device__ float               s_score[NTOT];
__device__ int                 s_label[NTOT];
__device__ float               s_box  [NTOT][4];
__device__ unsigned long long  g_mask [NTOT][NW];
__device__ int                 g_dummy;

__constant__ int   c_HW[3]   = {65536, 16384, 4096};
__constant__ int   c_W[3]    = {256, 128, 64};
__constant__ float c_strd[3] = {8.0f, 16.0f, 32.0f};

// ---------------- kernels ----------------

__device__ __forceinline__ float sigm(float x) { return 1.0f / (1.0f + expf(-x)); }

// marker no-op (slot alignment so ncu's fixed capture slot lands on decode)
__global__ void marker_kernel(int v) { if (threadIdx.x == 1025) g_dummy = v; }

// fused decode, high-MLP: 1 thread/pixel, class loop in batches of 16
__global__ void __launch_bounds__(256) decode_all_kernel(
        const float* __restrict__ cls0,
        const float* __restrict__ cls1,
        const float* __restrict__ cls2,
        const float* __restrict__ ctn0,
        const float* __restrict__ ctn1,
        const float* __restrict__ ctn2) {
    int blk = blockIdx.x;
    int lv; const float* cls; const float* ctn; int HW;
    if (blk < 256)      { lv = 0; cls = cls0; ctn = ctn0; HW = 65536; }
    else if (blk < 320) { lv = 1; cls = cls1; ctn = ctn1; HW = 16384; blk -= 256; }
    else                { lv = 2; cls = cls2; ctn = ctn2; HW = 4096;  blk -= 320; }
    int i = blk * 256 + threadIdx.x;
    if (i >= HW) return;

    const float* p = cls + i;
    float m = -1e30f;
    int lab = 0;
    #pragma unroll
    for (int c0 = 0; c0 < 80; c0 += 16) {
        float v[16];
        #pragma unroll
        for (int k = 0; k < 16; k++) v[k] = p[(c0 + k) * HW];  // 16 independent loads
        #pragma unroll
        for (int k = 0; k < 16; k++)
            if (v[k] > m) { m = v[k]; lab = c0 + k; }          // in-order: first-max
    }

    float sc = sqrtf(sigm(m) * sigm(ctn[i]));
    g_bits[lv][i]  = __float_as_uint(sc);   // sc in (0,1): bits monotone in value
    g_label[lv][i] = lab;
}

// One block per level: THREE 256-bucket refinement passes (exact 24-bit bucket
// threshold -> ncand ~ 1000+eps), compact, rank-count, emit topk.
__global__ void __launch_bounds__(1024) topk_level_kernel(
        const float* __restrict__ reg0,
        const float* __restrict__ reg1,
        const float* __restrict__ reg2,
        const float* __restrict__ scales) {
    int lv = blockIdx.x;
    const float* reg = (lv == 0) ? reg0 : (lv == 1) ? reg1 : reg2;
    int HW = c_HW[lv], W = c_W[lv];
    float stride = c_strd[lv];
    int tid = threadIdx.x;
    int n4 = HW >> 2;
    const uint4* b4 = (const uint4*)g_bits[lv];

    __shared__ unsigned hist[256];
    __shared__ unsigned suf[256];
    __shared__ int      sh_B;
    __shared__ unsigned sh_above;
    __shared__ int      sh_cnt;
    __shared__ unsigned long long skey[1024];

    // ---- pass 1: coarse hist over bits>>24 ----
    if (tid < 256) hist[tid] = 0u;
    __syncthreads();
    for (int i = tid; i < n4; i += 1024) {
        uint4 v = b4[i];
        atomicAdd(&hist[v.x >> 24], 1u);
        atomicAdd(&hist[v.y >> 24], 1u);
        atomicAdd(&hist[v.z >> 24], 1u);
        atomicAdd(&hist[v.w >> 24], 1u);
    }
    __syncthreads();
    if (tid < 256) suf[tid] = hist[tid];
    __syncthreads();
    for (int off = 1; off < 256; off <<= 1) {
        unsigned add = (tid < 256 && tid + off < 256) ? suf[tid + off] : 0u;
        __syncthreads();
        if (tid < 256) suf[tid] += add;
        __syncthreads();
    }
    if (tid < 256) {
        bool ok  = suf[tid] >= (unsigned)TOPK;
        bool okn = (tid == 255) ? false : (suf[tid + 1] >= (unsigned)TOPK);
        if (ok && !okn) { sh_B = tid; sh_above = (tid == 255) ? 0u : suf[tid + 1]; }
    }
    __syncthreads();
    int B1 = sh_B;                 // 8-bit prefix
    unsigned above1 = sh_above;

    // ---- pass 2: hist over (bits>>16)&0xFF within prefix B1 ----
    if (tid < 256) hist[tid] = 0u;
    __syncthreads();
    for (int i = tid; i < n4; i += 1024) {
        uint4 v = b4[i];
        if ((int)(v.x >> 24) == B1) atomicAdd(&hist[(v.x >> 16) & 0xFF], 1u);
        if ((int)(v.y >> 24) == B1) atomicAdd(&hist[(v.y >> 16) & 0xFF], 1u);
        if ((int)(v.z >> 24) == B1) atomicAdd(&hist[(v.z >> 16) & 0xFF], 1u);
        if ((int)(v.w >> 24) == B1) atomicAdd(&hist[(v.w >> 16) & 0xFF], 1u);
    }
    __syncthreads();
    if (tid < 256) suf[tid] = hist[tid];
    __syncthreads();
    for (int off = 1; off < 256; off <<= 1) {
        unsigned add = (tid < 256 && tid + off < 256) ? suf[tid + off] : 0u;
        __syncthreads();
        if (tid < 256) suf[tid] += add;
        __syncthreads();
    }
    if (tid < 256) {
        bool ok  = above1 + suf[tid] >= (unsigned)TOPK;
        bool okn = (tid == 255) ? false : (above1 + suf[tid + 1] >= (unsigned)TOPK);
        if (ok && !okn) {
            sh_B = ((B1 << 8) | tid);                               // 16-bit prefix
            sh_above = above1 + ((tid == 255) ? 0u : suf[tid + 1]); // count above it
        }
    }
    __syncthreads();
    int B2 = sh_B;                 // 16-bit prefix
    unsigned above2 = sh_above;

    // ---- pass 3: hist over (bits>>8)&0xFF within prefix B2 ----
    if (tid < 256) hist[tid] = 0u;
    __syncthreads();
    for (int i = tid; i < n4; i += 1024) {
        uint4 v = b4[i];
        if ((int)(v.x >> 16) == B2) atomicAdd(&hist[(v.x >> 8) & 0xFF], 1u);
        if ((int)(v.y >> 16) == B2) atomicAdd(&hist[(v.y >> 8) & 0xFF], 1u);
        if ((int)(v.z >> 16) == B2) atomicAdd(&hist[(v.z >> 8) & 0xFF], 1u);
        if ((int)(v.w >> 16) == B2) atomicAdd(&hist[(v.w >> 8) & 0xFF], 1u);
    }
    __syncthreads();
    if (tid < 256) suf[tid] = hist[tid];
    __syncthreads();
    for (int off = 1; off < 256; off <<= 1) {
        unsigned add = (tid < 256 && tid + off < 256) ? suf[tid + off] : 0u;
        __syncthreads();
        if (tid < 256) suf[tid] += add;
        __syncthreads();
    }
    if (tid < 256) {
        bool ok  = above2 + suf[tid] >= (unsigned)TOPK;
        bool okn = (tid == 255) ? false : (above2 + suf[tid + 1] >= (unsigned)TOPK);
        if (ok && !okn) sh_B = ((B2 << 8) | tid);                   // 24-bit prefix
    }
    __syncthreads();
    unsigned thresh = ((unsigned)sh_B) << 8;

    // ---- compact: indices with bits >= thresh (order irrelevant) ----
    if (tid == 0) sh_cnt = 0;
    __syncthreads();
    for (int i4 = tid; i4 < n4; i4 += 1024) {
        uint4 v = b4[i4];
        int i = i4 * 4;
        if (v.x >= thresh) g_cand[lv][atomicAdd(&sh_cnt, 1)] = i;
        if (v.y >= thresh) g_cand[lv][atomicAdd(&sh_cnt, 1)] = i + 1;
        if (v.z >= thresh) g_cand[lv][atomicAdd(&sh_cnt, 1)] = i + 2;
        if (v.w >= thresh) g_cand[lv][atomicAdd(&sh_cnt, 1)] = i + 3;
    }
    __syncthreads();
    int ncand = sh_cnt;

    // ---- rank candidates (value desc, index asc) and emit topk rows ----
    float scl = scales[lv];
    for (int cbase = 0; cbase < ncand; cbase += 1024) {
        int c = cbase + tid;
        bool active = (c < ncand);
        unsigned mybits = 0; int myidx = 0;
        unsigned long long mykey = 0;
        if (active) {
            myidx  = g_cand[lv][c];
            mybits = g_bits[lv][myidx];
            mykey  = ((unsigned long long)mybits << 32) | (unsigned)(~(unsigned)myidx);
        }
        int rank = 0;
        for (int base = 0; base < ncand; base += 1024) {
            int j = base + tid;
            unsigned long long k = 0;
            if (j < ncand) {
                int ji = g_cand[lv][j];
                k = ((unsigned long long)g_bits[lv][ji] << 32) | (unsigned)(~(unsigned)ji);
            }
            __syncthreads();
            skey[tid] = k;
            __syncthreads();
            int lim = min(1024, ncand - base);
            if (active)
                for (int t = 0; t < lim; t++) rank += (skey[t] > mykey) ? 1 : 0;
        }
        if (active && rank < TOPK) {
            int o = lv * TOPK + rank;
            t_bits[o]  = mybits;
            t_label[o] = g_label[lv][myidx];
            int x = myidx % W, y = myidx / W;
            float ax = ((float)x + 0.5f) * stride;
            float ay = ((float)y + 0.5f) * stride;
            float r0 = fmaxf(reg[0 * HW + myidx] * scl, 0.0f) * stride;
            float r1 = fmaxf(reg[1 * HW + myidx] * scl, 0.0f) * stride;
            float r2 = fmaxf(reg[2 * HW + myidx] * scl, 0.0f) * stride;
            float r3 = fmaxf(reg[3 * HW + myidx] * scl, 0.0f) * stride;
            t_box[o][0] = ax - r0; t_box[o][1] = ay - r1;
            t_box[o][2] = ax + r2; t_box[o][3] = ay + r3;
        }
        __syncthreads();
    }
}

// stable argsort(-scores) over the 3000 concatenated entries via rank counting
__global__ void rank_global_kernel() {
    int g = blockIdx.x * blockDim.x + threadIdx.x;
    __shared__ unsigned long long skey[256];
    bool active = (g < NTOT);
    unsigned long long mykey = 0;
    if (active) mykey = ((unsigned long long)t_bits[g] << 32) | (unsigned)(~(unsigned)g);
    int rank = 0;
    for (int base = 0; base < NTOT; base += 256) {
        int j = base + (int)threadIdx.x;
        unsigned long long k = 0;
        if (j < NTOT) k = ((unsigned long long)t_bits[j] << 32) | (unsigned)(~(unsigned)j);
        __syncthreads();
        skey[threadIdx.x] = k;
        __syncthreads();
        int lim = min(256, NTOT - base);
        if (active)
            for (int t = 0; t < lim; t++) rank += (skey[t] > mykey) ? 1 : 0;
    }
    if (active) {
        s_score[rank] = __uint_as_float(t_bits[g]);
        s_label[rank] = t_label[g];
        s_box[rank][0] = t_box[g][0];
        s_box[rank][1] = t_box[g][1];
        s_box[rank][2] = t_box[g][2];
        s_box[rank][3] = t_box[g][3];
    }
}

// suppression bitmask: bit j (j>i) set iff IoU(i,j) > 0.6
// triangle-pruned (skipped blocks are provably never read); exact IoU math
__global__ void mask_kernel() {
    int w  = blockIdx.x;                 // word 0..46  (j in [64w, 64w+64))
    int by = blockIdx.y;                 // i-block     (i in [256by, 256by+256))
    if (w < 4 * by) return;              // all j < all i in this block: never read
    __shared__ float jb[64][4];
    __shared__ float ja[64];
    int jlim = min(64, NTOT - w * 64);
    if ((int)threadIdx.x < jlim) {
        int j = w * 64 + threadIdx.x;
        float x1 = s_box[j][0], y1 = s_box[j][1], x2 = s_box[j][2], y2 = s_box[j][3];
        jb[threadIdx.x][0] = x1; jb[threadIdx.x][1] = y1;
        jb[threadIdx.x][2] = x2; jb[threadIdx.x][3] = y2;
        ja[threadIdx.x] = (x2 - x1) * (y2 - y1);
    }
    __syncthreads();
    int i = by * 256 + threadIdx.x;
    if (i >= NTOT) return;
    float ix1 = s_box[i][0], iy1 = s_box[i][1], ix2 = s_box[i][2], iy2 = s_box[i][3];
    float ia = (ix2 - ix1) * (iy2 - iy1);
    unsigned long long bits = 0;
    for (int b = 0; b < jlim; b++) {
        int j = w * 64 + b;
        if (j > i) {
            float xx1 = fmaxf(ix1, jb[b][0]);
            float yy1 = fmaxf(iy1, jb[b][1]);
            float xx2 = fminf(ix2, jb[b][2]);
            float yy2 = fminf(iy2, jb[b][3]);
            float ww = fmaxf(1e-10f, xx2 - xx1);
            float hh = fmaxf(1e-10f, yy2 - yy1);
            float inter = ww * hh;
            float iou = inter / (ia + ja[b] - inter + 1e-14f);
            if (iou > NMS_TH) bits |= (1ull << b);
        }
    }
    g_mask[i][w] = bits;
}

__device__ __forceinline__ unsigned long long warp_or64(unsigned long long v) {
    #pragma unroll
    for (int o = 16; o; o >>= 1) v |= __shfl_xor_sync(0xFFFFFFFFu, v, o);
    return v;
}

// Pipelined greedy NMS: 24 warps, warp k owns words {2k, 2k+1}.
__global__ void __launch_bounds__(768) nms_finalize_kernel(float* __restrict__ out) {
    __shared__ unsigned long long  sh_kept[NW];
    __shared__ unsigned long long  sh_remv[NW];
    __shared__ volatile int        sh_flag[NW];
    __shared__ unsigned long long  colbuf[24][64];
    int tid  = threadIdx.x;           // 768
    int warp = tid >> 5, lane = tid & 31;
    if (tid < NW) sh_flag[tid] = 0;
    __syncthreads();

    int w0 = warp * 2;
    int w1 = w0 + 1;                   // may be 47 (invalid for warp 23)
    bool has1 = (w1 < NW);
    int last = has1 ? w1 : w0;

    unsigned long long acc0 = 0ull, acc1 = 0ull;
    int rA = lane, rB = lane + 32;     // row offsets within a 64-block

    for (int c = 0; c <= last; c++) {
        int base = c * 64;
        unsigned long long m00 = (base + rA < NTOT) ? g_mask[base + rA][w0] : 0ull;
        unsigned long long m01 = (base + rB < NTOT) ? g_mask[base + rB][w0] : 0ull;
        unsigned long long m10 = 0ull, m11 = 0ull;
        if (has1) {
            m10 = (base + rA < NTOT) ? g_mask[base + rA][w1] : 0ull;
            m11 = (base + rB < NTOT) ? g_mask[base + rB][w1] : 0ull;
        }
        unsigned long long kept;
        if (c == w0 || c == w1) {
            unsigned long long mA = (c == w0) ? m00 : m10;
            unsigned long long mB = (c == w0) ? m01 : m11;
            colbuf[warp][lane]      = mA;
            colbuf[warp][lane + 32] = mB;
            __syncwarp();
            unsigned long long r = warp_or64((c == w0) ? acc0 : acc1);
            unsigned long long k0 = 0ull;
            if (lane == 0) {
                int lim = min(64, NTOT - base);
                #pragma unroll
                for (int b = 0; b < 64; b++) {
                    unsigned long long v = colbuf[warp][b];   // addr indep of r
                    if (!((r >> b) & 1ull)) { k0 |= (1ull << b); r |= v; }
                }
                if (lim < 64) k0 &= (1ull << lim) - 1ull;
                sh_remv[c] = r;
                sh_kept[c] = k0;
                __threadfence_block();
                sh_flag[c] = 1;
            }
            kept = __shfl_sync(0xFFFFFFFFu, k0, 0);
            __syncwarp();
        } else {
            while (sh_flag[c] == 0) {}
            __threadfence_block();
            kept = sh_kept[c];
        }
        if (c < w0) {
            acc0 |= (((kept >> rA) & 1ull) ? m00 : 0ull)
                  | (((kept >> rB) & 1ull) ? m01 : 0ull);
        }
        if (has1 && c < w1) {
            acc1 |= (((kept >> rA) & 1ull) ? m10 : 0ull)
                  | (((kept >> rB) & 1ull) ? m11 : 0ull);
        }
    }
    __syncthreads();

    // fused finalize: [boxes 12000][scores 3000][labels 3000][keep 3000] all f32
    for (int i = tid; i < NTOT; i += 768) {
        out[i * 4 + 0] = s_box[i][0];
        out[i * 4 + 1] = s_box[i][1];
        out[i * 4 + 2] = s_box[i][2];
        out[i * 4 + 3] = s_box[i][3];
        float sc = s_score[i];
        out[12000 + i] = sc;
        out[15000 + i] = (float)s_label[i];
        bool kp = !((sh_remv[i >> 6] >> (i & 63)) & 1ull) && (sc > CONF_TH);
        out[18000 + i] = kp ? 1.0f : 0.0f;
    }
}

// ---------------- launch ----------------
extern "C" void kernel_launch(void* const* d_in, const int* in_sizes, int n_in,
                              void* d_out, int out_size) {
    const float *cls[3], *reg[3], *ctn[3], *scales;
    if (in_sizes[1] == 262144) {
        cls[0] = (const float*)d_in[0]; reg[0] = (const float*)d_in[1]; ctn[0] = (const float*)d_in[2];
        cls[1] = (const float*)d_in[3]; reg[1] = (const float*)d_in[4]; ctn[1] = (const float*)d_in[5];
        cls[2] = (const float*)d_in[6]; reg[2] = (const float*)d_in[7]; ctn[2] = (const float*)d_in[8];
        scales = (const float*)d_in[9];
    } else if (in_sizes[3] == 262144) {
        cls[0] = (const float*)d_in[0]; cls[1] = (const float*)d_in[1]; cls[2] = (const float*)d_in[2];
        reg[0] = (const float*)d_in[3]; reg[1] = (const float*)d_in[4]; reg[2] = (const float*)d_in[5];
        ctn[0] = (const float*)d_in[6]; ctn[1] = (const float*)d_in[7]; ctn[2] = (const float*)d_in[8];
        scales = (const float*)d_in[9];
    } else {
        cls[0] = (const float*)d_in[0]; cls[1] = (const float*)d_in[1]; cls[2] = (const float*)d_in[2];
        ctn[0] = (const float*)d_in[3]; ctn[1] = (const float*)d_in[4]; ctn[2] = (const float*)d_in[5];
        reg[0] = (const float*)d_in[6]; reg[1] = (const float*)d_in[7]; reg[2] = (const float*)d_in[8];
        scales = (const float*)d_in[9];
    }

    // 3 markers shift ncu's fixed capture slot (#4) onto decode_all_kernel
    marker_kernel<<<1, 32>>>(1);
    marker_kernel<<<1, 32>>>(2);
    marker_kernel<<<1, 32>>>(3);
    decode_all_kernel<<<256 + 64 + 16, 256>>>(cls[0], cls[1], cls[2],
                                              ctn[0], ctn[1], ctn[2]);
    topk_level_kernel<<<3, 1024>>>(reg[0], reg[1], reg[2], scales);
    rank_global_kernel<<<(NTOT + 255) / 256, 256>>>();
    {
        dim3 grid(NW, (NTOT + 255) / 256);
        mask_kernel<<<grid, 256>>>();
    }
    nms_finalize_kernel<<<1, 768>>>((float*)d_out);
}